// round 16
// baseline (speedup 1.0000x reference)
#include <cuda_runtime.h>
#include <cuda_bf16.h>

// TensorRepsTransform: per row n (N=65536, DIM=832)
//   out[0:64)         = t[0:64)                                   (order-0, even)
//   out[64+4s+j)      = sign(det L) * sum_k L[j][k] t[64+4s+k]    (order-1, odd)
//   out[320+16s+4a+b) = sum_{k1,k2} L[a][k1] L[b][k2] t[320+16s+4k1+4k2]  (order-2, even)
//
// Converged R6 body (one warp per row, 7 front-batched coalesced float4
// streaming loads, order-2 exchanged in 4-lane shuffle groups, streaming
// stores) at 128 threads/block — the one unprobed geometry point (512 was
// worse, 256 is the measured plateau). Kernel runs at ~89% of effective
// spec HBM bandwidth; HBM R/W-mix service is the hard ceiling.

#define ROW_DIM 832
#define TPB 128

__global__ __launch_bounds__(TPB) void trep_kernel(
    const float* __restrict__ tens,
    const float* __restrict__ lfr,
    float* __restrict__ out,
    int nrows)
{
    const int gwarp = (int)((blockIdx.x * (unsigned)TPB + threadIdx.x) >> 5);
    const int lane  = threadIdx.x & 31;
    if (gwarp >= nrows) return;

    const float* __restrict__ tr   = tens + (size_t)gwarp * ROW_DIM;
    float* __restrict__       orow = out  + (size_t)gwarp * ROW_DIM;

    // ---- front-batched loads (max per-warp MLP) ----
    // L first: det/sgn feeds the earliest stores.
    const float4* Lp = (const float4*)(lfr + (size_t)gwarp * 16);
    float4 Lr0 = Lp[0], Lr1 = Lp[1], Lr2 = Lp[2], Lr3 = Lp[3];

    // order-2: 128 float4, 4 per lane (coalesced)
    float4 t0 = __ldcs(((const float4*)(tr + 320)) + lane);
    float4 t1 = __ldcs(((const float4*)(tr + 320)) + lane + 32);
    float4 t2 = __ldcs(((const float4*)(tr + 320)) + lane + 64);
    float4 t3 = __ldcs(((const float4*)(tr + 320)) + lane + 96);

    // order-1: 64 float4, 2 per lane (coalesced)
    float4 v1 = __ldcs(((const float4*)(tr + 64)) + lane);
    float4 v2 = __ldcs(((const float4*)(tr + 64)) + lane + 32);

    // order-0 passthrough: load + immediate store, no long-lived register
    if (lane < 16) {
        float4 q0 = __ldcs(((const float4*)tr) + lane);
        __stcs(((float4*)orow) + lane, q0);
    }

    float L00=Lr0.x, L01=Lr0.y, L02=Lr0.z, L03=Lr0.w;
    float L10=Lr1.x, L11=Lr1.y, L12=Lr1.z, L13=Lr1.w;
    float L20=Lr2.x, L21=Lr2.y, L22=Lr2.z, L23=Lr2.w;
    float L30=Lr3.x, L31=Lr3.y, L32=Lr3.z, L33=Lr3.w;

    // ---- det(L) sign ----
    float det =
          (L00*L11 - L01*L10) * (L22*L33 - L23*L32)
        - (L00*L12 - L02*L10) * (L21*L33 - L23*L31)
        + (L00*L13 - L03*L10) * (L21*L32 - L22*L31)
        + (L01*L12 - L02*L11) * (L20*L33 - L23*L30)
        - (L01*L13 - L03*L11) * (L20*L32 - L22*L30)
        + (L02*L13 - L03*L12) * (L20*L31 - L21*L30);
    float sgn = (det > 0.0f) ? 1.0f : ((det < 0.0f) ? -1.0f : 0.0f);

    // ---- order-1: y = sgn * (L v), 2 slots per lane ----
    {
        float4 y;
        y.x = sgn * (L00*v1.x + L01*v1.y + L02*v1.z + L03*v1.w);
        y.y = sgn * (L10*v1.x + L11*v1.y + L12*v1.z + L13*v1.w);
        y.z = sgn * (L20*v1.x + L21*v1.y + L22*v1.z + L23*v1.w);
        y.w = sgn * (L30*v1.x + L31*v1.y + L32*v1.z + L33*v1.w);
        __stcs(((float4*)(orow + 64)) + lane, y);

        y.x = sgn * (L00*v2.x + L01*v2.y + L02*v2.z + L03*v2.w);
        y.y = sgn * (L10*v2.x + L11*v2.y + L12*v2.z + L13*v2.w);
        y.z = sgn * (L20*v2.x + L21*v2.y + L22*v2.z + L23*v2.w);
        y.w = sgn * (L30*v2.x + L31*v2.y + L32*v2.z + L33*v2.w);
        __stcs(((float4*)(orow + 64)) + lane + 32, y);
    }

    // ---- order-2: U = L (T L^T), cooperative in 4-lane groups ----
    // float4 #g of the order-2 block is row (g&3) of slot (g>>2).
    const int r = lane & 3;
    float4 Lrow = (r == 0) ? Lr0 : (r == 1) ? Lr1 : (r == 2) ? Lr2 : Lr3;

    #pragma unroll
    for (int a = 0; a < 4; a++) {
        float4 Ta = (a == 0) ? t0 : (a == 1) ? t1 : (a == 2) ? t2 : t3;

        // B[m] = sum_k L[m][k] * T[r][k]   (local)
        float4 B;
        B.x = L00*Ta.x + L01*Ta.y + L02*Ta.z + L03*Ta.w;
        B.y = L10*Ta.x + L11*Ta.y + L12*Ta.z + L13*Ta.w;
        B.z = L20*Ta.x + L21*Ta.y + L22*Ta.z + L23*Ta.w;
        B.w = L30*Ta.x + L31*Ta.y + L32*Ta.z + L33*Ta.w;

        // U[r][m] = sum_{r'} L[r][r'] * B_{r'}[m]   (width-4 shuffles)
        float4 U = make_float4(0.f, 0.f, 0.f, 0.f);
        #pragma unroll
        for (int rp = 0; rp < 4; rp++) {
            float bx = __shfl_sync(0xffffffffu, B.x, rp, 4);
            float by = __shfl_sync(0xffffffffu, B.y, rp, 4);
            float bz = __shfl_sync(0xffffffffu, B.z, rp, 4);
            float bw = __shfl_sync(0xffffffffu, B.w, rp, 4);
            float c = (rp == 0) ? Lrow.x : (rp == 1) ? Lrow.y
                    : (rp == 2) ? Lrow.z : Lrow.w;
            U.x += c * bx;
            U.y += c * by;
            U.z += c * bz;
            U.w += c * bw;
        }
        __stcs(((float4*)(orow + 320)) + 32 * a + lane, U);
    }
}

extern "C" void kernel_launch(void* const* d_in, const int* in_sizes, int n_in,
                              void* d_out, int out_size)
{
    const float* tens = (const float*)d_in[0];   // (N, 832) float32
    const float* lfr  = (const float*)d_in[1];   // (N, 4, 4) float32
    // d_in[2] = parity_odd mask: compile-time constant of REPS, folded into layout.
    (void)n_in; (void)out_size;

    int nrows = in_sizes[0] / ROW_DIM;           // 65536
    float* out = (float*)d_out;

    int nblocks = (nrows * 32 + TPB - 1) / TPB;  // one warp per row
    trep_kernel<<<nblocks, TPB>>>(tens, lfr, out, nrows);
}

// round 17
// speedup vs baseline: 1.0018x; 1.0018x over previous
#include <cuda_runtime.h>
#include <cuda_bf16.h>

// TensorRepsTransform: per row n (N=65536, DIM=832)
//   out[0:64)         = t[0:64)                                   (order-0, even)
//   out[64+4s+j)      = sign(det L) * sum_k L[j][k] t[64+4s+k]    (order-1, odd)
//   out[320+16s+4a+b) = sum_{k1,k2} L[a][k1] L[b][k2] t[320+16s+4k1+4k2]  (order-2, even)
//
// FINAL converged kernel (16 rounds, 11 levers measured; best config):
// one warp per row, 256 threads/block, 7 front-batched coalesced float4
// streaming loads, order-2 rows exchanged in 4-lane shuffle groups,
// streaming stores. Runs at ~89% of effective spec HBM bandwidth; the HBM
// read/write-mix service rate is the hard ceiling — DRAM% is invariant
// across occupancy, per-warp MLP, cp.async staging, L2 prefetch, persistent
// grids, cache policies, 256-bit memory ops, and CTA geometry.

#define ROW_DIM 832

__global__ __launch_bounds__(256) void trep_kernel(
    const float* __restrict__ tens,
    const float* __restrict__ lfr,
    float* __restrict__ out,
    int nrows)
{
    const int gwarp = (int)((blockIdx.x * 256u + threadIdx.x) >> 5);
    const int lane  = threadIdx.x & 31;
    if (gwarp >= nrows) return;

    const float* __restrict__ tr   = tens + (size_t)gwarp * ROW_DIM;
    float* __restrict__       orow = out  + (size_t)gwarp * ROW_DIM;

    // ---- front-batched loads (max per-warp MLP) ----
    // L first: det/sgn feeds the earliest stores.
    const float4* Lp = (const float4*)(lfr + (size_t)gwarp * 16);
    float4 Lr0 = Lp[0], Lr1 = Lp[1], Lr2 = Lp[2], Lr3 = Lp[3];

    // order-2: 128 float4, 4 per lane (coalesced)
    float4 t0 = __ldcs(((const float4*)(tr + 320)) + lane);
    float4 t1 = __ldcs(((const float4*)(tr + 320)) + lane + 32);
    float4 t2 = __ldcs(((const float4*)(tr + 320)) + lane + 64);
    float4 t3 = __ldcs(((const float4*)(tr + 320)) + lane + 96);

    // order-1: 64 float4, 2 per lane (coalesced)
    float4 v1 = __ldcs(((const float4*)(tr + 64)) + lane);
    float4 v2 = __ldcs(((const float4*)(tr + 64)) + lane + 32);

    // order-0 passthrough: load + immediate store, no long-lived register
    if (lane < 16) {
        float4 q0 = __ldcs(((const float4*)tr) + lane);
        __stcs(((float4*)orow) + lane, q0);
    }

    float L00=Lr0.x, L01=Lr0.y, L02=Lr0.z, L03=Lr0.w;
    float L10=Lr1.x, L11=Lr1.y, L12=Lr1.z, L13=Lr1.w;
    float L20=Lr2.x, L21=Lr2.y, L22=Lr2.z, L23=Lr2.w;
    float L30=Lr3.x, L31=Lr3.y, L32=Lr3.z, L33=Lr3.w;

    // ---- det(L) sign ----
    float det =
          (L00*L11 - L01*L10) * (L22*L33 - L23*L32)
        - (L00*L12 - L02*L10) * (L21*L33 - L23*L31)
        + (L00*L13 - L03*L10) * (L21*L32 - L22*L31)
        + (L01*L12 - L02*L11) * (L20*L33 - L23*L30)
        - (L01*L13 - L03*L11) * (L20*L32 - L22*L30)
        + (L02*L13 - L03*L12) * (L20*L31 - L21*L30);
    float sgn = (det > 0.0f) ? 1.0f : ((det < 0.0f) ? -1.0f : 0.0f);

    // ---- order-1: y = sgn * (L v), 2 slots per lane ----
    {
        float4 y;
        y.x = sgn * (L00*v1.x + L01*v1.y + L02*v1.z + L03*v1.w);
        y.y = sgn * (L10*v1.x + L11*v1.y + L12*v1.z + L13*v1.w);
        y.z = sgn * (L20*v1.x + L21*v1.y + L22*v1.z + L23*v1.w);
        y.w = sgn * (L30*v1.x + L31*v1.y + L32*v1.z + L33*v1.w);
        __stcs(((float4*)(orow + 64)) + lane, y);

        y.x = sgn * (L00*v2.x + L01*v2.y + L02*v2.z + L03*v2.w);
        y.y = sgn * (L10*v2.x + L11*v2.y + L12*v2.z + L13*v2.w);
        y.z = sgn * (L20*v2.x + L21*v2.y + L22*v2.z + L23*v2.w);
        y.w = sgn * (L30*v2.x + L31*v2.y + L32*v2.z + L33*v2.w);
        __stcs(((float4*)(orow + 64)) + lane + 32, y);
    }

    // ---- order-2: U = L (T L^T), cooperative in 4-lane groups ----
    // float4 #g of the order-2 block is row (g&3) of slot (g>>2).
    const int r = lane & 3;
    float4 Lrow = (r == 0) ? Lr0 : (r == 1) ? Lr1 : (r == 2) ? Lr2 : Lr3;

    #pragma unroll
    for (int a = 0; a < 4; a++) {
        float4 Ta = (a == 0) ? t0 : (a == 1) ? t1 : (a == 2) ? t2 : t3;

        // B[m] = sum_k L[m][k] * T[r][k]   (local)
        float4 B;
        B.x = L00*Ta.x + L01*Ta.y + L02*Ta.z + L03*Ta.w;
        B.y = L10*Ta.x + L11*Ta.y + L12*Ta.z + L13*Ta.w;
        B.z = L20*Ta.x + L21*Ta.y + L22*Ta.z + L23*Ta.w;
        B.w = L30*Ta.x + L31*Ta.y + L32*Ta.z + L33*Ta.w;

        // U[r][m] = sum_{r'} L[r][r'] * B_{r'}[m]   (width-4 shuffles)
        float4 U = make_float4(0.f, 0.f, 0.f, 0.f);
        #pragma unroll
        for (int rp = 0; rp < 4; rp++) {
            float bx = __shfl_sync(0xffffffffu, B.x, rp, 4);
            float by = __shfl_sync(0xffffffffu, B.y, rp, 4);
            float bz = __shfl_sync(0xffffffffu, B.z, rp, 4);
            float bw = __shfl_sync(0xffffffffu, B.w, rp, 4);
            float c = (rp == 0) ? Lrow.x : (rp == 1) ? Lrow.y
                    : (rp == 2) ? Lrow.z : Lrow.w;
            U.x += c * bx;
            U.y += c * by;
            U.z += c * bz;
            U.w += c * bw;
        }
        __stcs(((float4*)(orow + 320)) + 32 * a + lane, U);
    }
}

extern "C" void kernel_launch(void* const* d_in, const int* in_sizes, int n_in,
                              void* d_out, int out_size)
{
    const float* tens = (const float*)d_in[0];   // (N, 832) float32
    const float* lfr  = (const float*)d_in[1];   // (N, 4, 4) float32
    // d_in[2] = parity_odd mask: compile-time constant of REPS, folded into layout.
    (void)n_in; (void)out_size;

    int nrows = in_sizes[0] / ROW_DIM;           // 65536
    float* out = (float*)d_out;

    int nblocks = (nrows * 32 + 255) / 256;      // one warp per row
    trep_kernel<<<nblocks, 256>>>(tens, lfr, out, nrows);
}